// round 1
// baseline (speedup 1.0000x reference)
#include <cuda_runtime.h>
#include <cuda_bf16.h>

#define NV 10000
#define BB 8
#define NE 2000000
#define NB (NV * BB)

// Scratch in [N, B] (node-major, batch-contiguous) layout: each node's 8 batch
// values occupy one 32-byte chunk -> float4-pair gathers and red.v4 scatters.
__device__ float g_xt[NB];    // x transposed
__device__ float g_fx[NB];    // tanh(x)
__device__ float g_pred[NB];  // scatter accumulator (by tgt)
__device__ float g_err[NB];   // x - pred
__device__ float g_aggr[NB];  // scatter accumulator (by src)
__device__ int   g_idx64;     // 1 if edge_index is int64, 0 if int32

// ---------------------------------------------------------------------------
// Detect edge_index dtype: values are in [0, 10000), so if stored as int64
// (little-endian) every odd 32-bit word is 0. For int32 data, the probability
// that 64 sampled words are all zero is ~1e-256.
__global__ void detect_kernel(const unsigned int* __restrict__ ei_words) {
    if (blockIdx.x == 0 && threadIdx.x == 0) {
        int is64 = 1;
        #pragma unroll
        for (int i = 0; i < 64; i++) {
            if (ei_words[2 * i + 1] != 0u) { is64 = 0; break; }
        }
        g_idx64 = is64;
    }
}

// ---------------------------------------------------------------------------
__global__ void prep_kernel(const float* __restrict__ values) {
    int idx = blockIdx.x * blockDim.x + threadIdx.x;
    if (idx >= NB) return;
    int n = idx >> 3;
    int b = idx & 7;
    float x = values[b * NV + n];
    float fx = tanhf(x);
    g_xt[idx]   = x;
    g_fx[idx]   = fx;
    g_pred[idx] = 0.0f;
    g_aggr[idx] = 0.0f;
}

// ---------------------------------------------------------------------------
__device__ __forceinline__ void red_add_v4(float* p, float4 v) {
    asm volatile("red.global.add.v4.f32 [%0], {%1, %2, %3, %4};"
                 :: "l"(p), "f"(v.x), "f"(v.y), "f"(v.z), "f"(v.w)
                 : "memory");
}

__device__ __forceinline__ void load_edge(const void* ei, int e, int& s, int& t) {
    if (g_idx64) {
        const long long* p = (const long long*)ei;
        s = (int)p[e];
        t = (int)p[NE + e];
    } else {
        const int* p = (const int*)ei;
        s = p[e];
        t = p[NE + e];
    }
}

// pass1: pred[tgt] += w * fx[src]   (all 8 batches via 2x red.v4)
__global__ void pass1_kernel(const void* __restrict__ ei,
                             const float* __restrict__ w) {
    int e = blockIdx.x * blockDim.x + threadIdx.x;
    if (e >= NE) return;
    int s, t;
    load_edge(ei, e, s, t);
    float we = w[e];
    const float4* f = reinterpret_cast<const float4*>(g_fx) + (size_t)s * 2;
    float4 a = f[0], b = f[1];
    float* p = g_pred + (size_t)t * 8;
    red_add_v4(p,     make_float4(we * a.x, we * a.y, we * a.z, we * a.w));
    red_add_v4(p + 4, make_float4(we * b.x, we * b.y, we * b.z, we * b.w));
}

// ---------------------------------------------------------------------------
__global__ void err_kernel() {
    int idx = blockIdx.x * blockDim.x + threadIdx.x;
    if (idx >= NB) return;
    g_err[idx] = g_xt[idx] - g_pred[idx];
}

// pass2: aggr[src] += w * err[tgt]
__global__ void pass2_kernel(const void* __restrict__ ei,
                             const float* __restrict__ w) {
    int e = blockIdx.x * blockDim.x + threadIdx.x;
    if (e >= NE) return;
    int s, t;
    load_edge(ei, e, s, t);
    float we = w[e];
    const float4* f = reinterpret_cast<const float4*>(g_err) + (size_t)t * 2;
    float4 a = f[0], b = f[1];
    float* p = g_aggr + (size_t)s * 8;
    red_add_v4(p,     make_float4(we * a.x, we * a.y, we * a.z, we * a.w));
    red_add_v4(p + 4, make_float4(we * b.x, we * b.y, we * b.z, we * b.w));
}

// ---------------------------------------------------------------------------
// out layout: [3, B*N] with inner layout [B, N] (row b, node n at b*N + n)
__global__ void final_kernel(float* __restrict__ out) {
    int idx = blockIdx.x * blockDim.x + threadIdx.x;
    if (idx >= NB) return;
    int n = idx >> 3;
    int b = idx & 7;
    float pred = g_pred[idx];
    float err  = g_err[idx];
    float fx   = g_fx[idx];
    float dx   = err - (1.0f - fx * fx) * g_aggr[idx];
    int o = b * NV + n;
    out[o]          = pred;
    out[NB + o]     = err;
    out[2 * NB + o] = dx;
}

// ---------------------------------------------------------------------------
extern "C" void kernel_launch(void* const* d_in, const int* in_sizes, int n_in,
                              void* d_out, int out_size) {
    const float* values  = (const float*)d_in[0];
    const float* weights = (const float*)d_in[1];
    const void*  ei      = (const void*)d_in[2];
    float* out = (float*)d_out;

    const int TB = 256;
    detect_kernel<<<1, 32>>>((const unsigned int*)ei);
    prep_kernel<<<(NB + TB - 1) / TB, TB>>>(values);
    pass1_kernel<<<(NE + TB - 1) / TB, TB>>>(ei, weights);
    err_kernel<<<(NB + TB - 1) / TB, TB>>>();
    pass2_kernel<<<(NE + TB - 1) / TB, TB>>>(ei, weights);
    final_kernel<<<(NB + TB - 1) / TB, TB>>>(out);
}